// round 17
// baseline (speedup 1.0000x reference)
#include <cuda_runtime.h>
#include <cuda_fp16.h>
#include <math.h>
#include <stdint.h>

// ---------------------------------------------------------------------------
// GraphTransformer layer: N=50000, E=600000, C=128, H=8, Dh=16
// Round 17: GEMM re-tiled BM=64 x BN=128 (warp tile 32x32, 32 acc regs,
// 3 CTAs/SM = 24 warps). BK=64, ldmatrix, stream overlap kept.
// ---------------------------------------------------------------------------

#define N_MAX 50000
#define E_MAX 600000

__device__ __half g_hln[(size_t)N_MAX * 128];
__device__ __half g_qkv[(size_t)N_MAX * 384];
__device__ __half g_eln[(size_t)E_MAX * 128];
__device__ __half g_ep [(size_t)E_MAX * 128];
__device__ float  g_dist[(size_t)E_MAX];
__device__ float  g_wV [(size_t)N_MAX * 128];
__device__ float  g_z  [(size_t)N_MAX * 8];
__device__ __half g_t  [(size_t)E_MAX * 256];
__device__ __half g_tn [(size_t)N_MAX * 256];
__device__ __half g_wT [229376];
__device__ int    g_is64;

// ---------------------------------------------------------------------------
// MMA + cp.async + ldmatrix primitives
// ---------------------------------------------------------------------------
__device__ __forceinline__ void mma_f16(float* c, const uint32_t* a,
                                        uint32_t b0, uint32_t b1) {
    asm volatile(
        "mma.sync.aligned.m16n8k16.row.col.f32.f16.f16.f32 "
        "{%0,%1,%2,%3}, {%4,%5,%6,%7}, {%8,%9}, {%0,%1,%2,%3};"
        : "+f"(c[0]), "+f"(c[1]), "+f"(c[2]), "+f"(c[3])
        : "r"(a[0]), "r"(a[1]), "r"(a[2]), "r"(a[3]), "r"(b0), "r"(b1));
}
__device__ __forceinline__ void ldsm_x4(uint32_t* r, uint32_t addr) {
    asm volatile("ldmatrix.sync.aligned.m8n8.x4.shared.b16 {%0,%1,%2,%3}, [%4];"
                 : "=r"(r[0]), "=r"(r[1]), "=r"(r[2]), "=r"(r[3]) : "r"(addr));
}
#define CP16(d, s, n) asm volatile("cp.async.cg.shared.global [%0], [%1], 16, %2;" :: "r"(d), "l"(s), "r"(n) : "memory")
#define CPCOMMIT()    asm volatile("cp.async.commit_group;" ::: "memory")
#define CPWAIT(n)     asm volatile("cp.async.wait_group %0;" :: "n"(n) : "memory")

#define SKH  72                          // halfs per smem row (64 data + 8 pad)
#define TA_H (64 * SKH)                  // A tile: 64 rows
#define TB_H (128 * SKH)                 // B tile: 128 rows
#define TA_B (TA_H * 2)
#define TB_B (TB_H * 2)
#define GEMM_DYN (2 * TA_B + 2 * TB_B)   // 55296 bytes

// ---------------------------------------------------------------------------
// 256-thread fp16 HMMA GEMM: CTA tile 64(M) x 128(N), BK=64, warps 2(M)x4(N),
// warp tile 32x32, double-buffered cp.async + ldmatrix. 3 CTAs/SM.
// Epilogues: +bias, +r1m*r1n, SiLU, +resid; optional fused output LayerNorm.
// ---------------------------------------------------------------------------
__global__ void __launch_bounds__(256, 3) mma_gemm(
    const __half* __restrict__ Ah, int lda,
    const __half* __restrict__ BT,
    float* __restrict__ Cf, __half* __restrict__ Ch,
    int M, int K, int ldc,
    const float* __restrict__ bias,
    const float* __restrict__ resid, int ldr,
    const float* __restrict__ r1m, const float* __restrict__ r1n,
    int act,
    const float* __restrict__ lng, const float* __restrict__ lnb,
    __half* __restrict__ lnout)
{
    extern __shared__ __half dyn[];
    __half* sA = dyn;                    // 2 stages of 64xSKH
    __half* sB = dyn + 2 * TA_H;         // 2 stages of 128xSKH
    __shared__ float red[64][4][2];

    const int tid = threadIdx.x;
    const int wid = tid >> 5;
    const int lane = tid & 31;
    const int warp_m = wid & 1;          // 2 over M (32 rows each)
    const int warp_n = wid >> 1;         // 4 over N (32 cols each)
    const int m0 = blockIdx.x * 64;
    const int n0 = blockIdx.y * 128;
    const int grp = lane >> 2;
    const int tig = lane & 3;

    const uint32_t sA0 = (uint32_t)__cvta_generic_to_shared(sA);
    const uint32_t sB0 = (uint32_t)__cvta_generic_to_shared(sB);
    const int lrow = tid >> 3;           // 0..31
    const int lj   = tid & 7;            // 16B granule

    // ldmatrix lane address components
    const int lr8  = lane & 7;
    const int aSel = (lane >> 3) & 1;
    const int aK   = (lane >> 4) * 8;
    const int bJ   = lane >> 4;
    const int bK   = ((lane >> 3) & 1) * 8;
    const uint32_t aOffH = (uint32_t)((warp_m * 32 + aSel * 8 + lr8) * SKH + aK);
    const uint32_t bOffH = (uint32_t)((warp_n * 32 + bJ * 8 + lr8) * SKH + bK);

    float acc[2][4][4];
    #pragma unroll
    for (int t = 0; t < 2; t++)
        #pragma unroll
        for (int j = 0; j < 4; j++)
            #pragma unroll
            for (int c = 0; c < 4; c++) acc[t][j][c] = 0.0f;

    const int nc = K >> 6;

    auto loadA = [&](int c, int buf) {
        const int k0 = c << 6;
        #pragma unroll
        for (int i = 0; i < 2; i++) {
            const int row = lrow + i * 32;
            const uint32_t dst = sA0 + buf * TA_B + row * (SKH * 2) + lj * 16;
            const int ok = (m0 + row) < M;
            const __half* src = Ah + (size_t)(ok ? (m0 + row) : 0) * lda + k0 + lj * 8;
            CP16(dst, src, ok ? 16 : 0);
        }
    };
    auto loadB = [&](int c, int buf) {
        const int k0 = c << 6;
        #pragma unroll
        for (int i = 0; i < 4; i++) {
            const int row = lrow + i * 32;
            const uint32_t dst = sB0 + buf * TB_B + row * (SKH * 2) + lj * 16;
            const __half* src = BT + (size_t)(n0 + row) * K + k0 + lj * 8;
            CP16(dst, src, 16);
        }
    };
    auto compute = [&](int buf) {
        const uint32_t abase = sA0 + buf * TA_B + aOffH * 2;
        const uint32_t bbase = sB0 + buf * TB_B + bOffH * 2;
        #pragma unroll
        for (int ks = 0; ks < 4; ks++) {
            const uint32_t koff = (uint32_t)(ks * 16 * 2);
            uint32_t a0[4], a1[4];
            ldsm_x4(a0, abase + koff);
            ldsm_x4(a1, abase + koff + 16 * SKH * 2);
            #pragma unroll
            for (int jp = 0; jp < 2; jp++) {
                uint32_t b[4];
                ldsm_x4(b, bbase + koff + (uint32_t)(jp * 16 * SKH * 2));
                mma_f16(acc[0][jp * 2 + 0], a0, b[0], b[1]);
                mma_f16(acc[1][jp * 2 + 0], a1, b[0], b[1]);
                mma_f16(acc[0][jp * 2 + 1], a0, b[2], b[3]);
                mma_f16(acc[1][jp * 2 + 1], a1, b[2], b[3]);
            }
        }
    };

    loadA(0, 0); loadB(0, 0); CPCOMMIT();
    for (int c = 0; c < nc; c++) {
        if (c + 1 < nc) {
            loadA(c + 1, (c + 1) & 1); loadB(c + 1, (c + 1) & 1);
            CPCOMMIT(); CPWAIT(1);
        } else CPWAIT(0);
        __syncthreads();
        compute(c & 1);
        __syncthreads();
    }

    if (lng == nullptr) {
        #pragma unroll
        for (int t = 0; t < 2; t++) {
            #pragma unroll
            for (int hh = 0; hh < 2; hh++) {
                const int m = m0 + warp_m * 32 + t * 16 + grp + hh * 8;
                if (m >= M) continue;
                const float r1 = r1m ? r1m[m] : 0.0f;
                const float* rrow = resid ? resid + (size_t)m * ldr : nullptr;
                #pragma unroll
                for (int j = 0; j < 4; j++) {
                    const int col = n0 + warp_n * 32 + j * 8 + tig * 2;
                    float v0 = acc[t][j][hh * 2 + 0];
                    float v1 = acc[t][j][hh * 2 + 1];
                    if (bias) { v0 += bias[col]; v1 += bias[col + 1]; }
                    if (r1m)  { v0 += r1 * r1n[col]; v1 += r1 * r1n[col + 1]; }
                    if (act) {
                        v0 = v0 / (1.0f + __expf(-v0));
                        v1 = v1 / (1.0f + __expf(-v1));
                    }
                    if (resid) { v0 += rrow[col]; v1 += rrow[col + 1]; }
                    if (Ch) {
                        *(__half2*)(Ch + (size_t)m * ldc + col) = __floats2half2_rn(v0, v1);
                    } else {
                        float2 o2; o2.x = v0; o2.y = v1;
                        *(float2*)(Cf + (size_t)m * ldc + col) = o2;
                    }
                }
            }
        }
    } else {
        // fused bias+resid -> Cf (fp32), then LayerNorm -> lnout (half)
        float s[2][2], sq[2][2];
        #pragma unroll
        for (int t = 0; t < 2; t++) {
            #pragma unroll
            for (int hh = 0; hh < 2; hh++) {
                const int m = m0 + warp_m * 32 + t * 16 + grp + hh * 8;
                const bool ok = m < M;
                const float* rrow = ok ? resid + (size_t)m * ldr : nullptr;
                float sum = 0.f, sumsq = 0.f;
                #pragma unroll
                for (int j = 0; j < 4; j++) {
                    const int col = warp_n * 32 + j * 8 + tig * 2;
                    float v0 = acc[t][j][hh * 2 + 0] + bias[col];
                    float v1 = acc[t][j][hh * 2 + 1] + bias[col + 1];
                    if (ok) { v0 += rrow[col]; v1 += rrow[col + 1]; }
                    acc[t][j][hh * 2 + 0] = v0;
                    acc[t][j][hh * 2 + 1] = v1;
                    if (ok) {
                        float2 o2; o2.x = v0; o2.y = v1;
                        *(float2*)(Cf + (size_t)m * ldc + col) = o2;
                    }
                    sum += v0 + v1;
                    sumsq += v0 * v0 + v1 * v1;
                }
                s[t][hh] = sum; sq[t][hh] = sumsq;
            }
        }
        #pragma unroll
        for (int t = 0; t < 2; t++)
            #pragma unroll
            for (int hh = 0; hh < 2; hh++) {
                s[t][hh]  += __shfl_xor_sync(0xffffffffu, s[t][hh], 1);
                s[t][hh]  += __shfl_xor_sync(0xffffffffu, s[t][hh], 2);
                sq[t][hh] += __shfl_xor_sync(0xffffffffu, sq[t][hh], 1);
                sq[t][hh] += __shfl_xor_sync(0xffffffffu, sq[t][hh], 2);
            }
        if (tig == 0) {
            #pragma unroll
            for (int t = 0; t < 2; t++)
                #pragma unroll
                for (int hh = 0; hh < 2; hh++) {
                    const int row = warp_m * 32 + t * 16 + hh * 8 + grp;
                    red[row][warp_n][0] = s[t][hh];
                    red[row][warp_n][1] = sq[t][hh];
                }
        }
        __syncthreads();
        #pragma unroll
        for (int t = 0; t < 2; t++) {
            #pragma unroll
            for (int hh = 0; hh < 2; hh++) {
                const int row = warp_m * 32 + t * 16 + hh * 8 + grp;
                const int m = m0 + row;
                if (m >= M) continue;
                const float S = red[row][0][0] + red[row][1][0] +
                                red[row][2][0] + red[row][3][0];
                const float Q = red[row][0][1] + red[row][1][1] +
                                red[row][2][1] + red[row][3][1];
                const float mu = S * (1.0f / 128.0f);
                const float var = Q * (1.0f / 128.0f) - mu * mu;
                const float rs = rsqrtf(var + 1e-5f);
                #pragma unroll
                for (int j = 0; j < 4; j++) {
                    const int col = warp_n * 32 + j * 8 + tig * 2;
                    float v0 = (acc[t][j][hh * 2 + 0] - mu) * rs * lng[col] + lnb[col];
                    float v1 = (acc[t][j][hh * 2 + 1] - mu) * rs * lng[col + 1] + lnb[col + 1];
                    *(__half2*)(lnout + (size_t)m * 128 + col) = __floats2half2_rn(v0, v1);
                }
            }
        }
    }
}

// ---------------------------------------------------------------------------
// Batched weight transpose to half
// ---------------------------------------------------------------------------
struct TransBatch {
    const float* src[10];
    __half* dst[10];
    int R[10], C[10];
};

__global__ void transpose_all(TransBatch tb)
{
    __shared__ float tile[32][33];
    const int i = blockIdx.z;
    const int R = tb.R[i], Cc = tb.C[i];
    const int c0 = blockIdx.x * 32, r0 = blockIdx.y * 32;
    if (c0 >= Cc || r0 >= R) return;
    const float* src = tb.src[i];
    __half* dst = tb.dst[i];
    int tx = threadIdx.x, ty = threadIdx.y;
    for (int dy = 0; dy < 32; dy += 8) {
        int r = r0 + ty + dy, c = c0 + tx;
        if (r < R && c < Cc) tile[ty + dy][tx] = src[(size_t)r * Cc + c];
    }
    __syncthreads();
    for (int dy = 0; dy < 32; dy += 8) {
        int c = c0 + ty + dy, r = r0 + tx;
        if (r < R && c < Cc) dst[(size_t)c * R + r] = __float2half_rn(tile[tx][ty + dy]);
    }
}

// ---------------------------------------------------------------------------
// misc kernels
// ---------------------------------------------------------------------------
__global__ void detect_kernel(const int* __restrict__ ei32)
{
    if (threadIdx.x == 0 && blockIdx.x == 0) {
        int any = 0;
        #pragma unroll 8
        for (int i = 0; i < 64; i++) any |= ei32[2 * i + 1];
        g_is64 = (any == 0) ? 1 : 0;
    }
}
__device__ __forceinline__ int edge_idx(const void* __restrict__ ei, long long pos)
{
    if (g_is64) return (int)((const long long*)ei)[pos];
    return ((const int*)ei)[pos];
}

__global__ void ln2_kernel(const float* __restrict__ x1,
                           const float* __restrict__ g1, const float* __restrict__ b1,
                           __half* __restrict__ o1, int M1,
                           const float* __restrict__ x2,
                           const float* __restrict__ g2, const float* __restrict__ b2,
                           __half* __restrict__ o2, int M2)
{
    int w = (blockIdx.x * blockDim.x + threadIdx.x) >> 5;
    int lane = threadIdx.x & 31;
    const float *x, *g, *b; __half* o; int row;
    if (w < M1) { x = x1; g = g1; b = b1; o = o1; row = w; }
    else if (w < M1 + M2) { x = x2; g = g2; b = b2; o = o2; row = w - M1; }
    else return;
    float4 v = *(const float4*)(x + (size_t)row * 128 + lane * 4);
    float s  = v.x + v.y + v.z + v.w;
    float sq = v.x*v.x + v.y*v.y + v.z*v.z + v.w*v.w;
    #pragma unroll
    for (int off = 16; off; off >>= 1) {
        s  += __shfl_xor_sync(0xffffffffu, s,  off);
        sq += __shfl_xor_sync(0xffffffffu, sq, off);
    }
    float mu  = s * (1.0f / 128.0f);
    float var = sq * (1.0f / 128.0f) - mu * mu;
    float rs  = rsqrtf(var + 1e-5f);
    float4 gv = *(const float4*)(g + lane * 4);
    float4 bv = *(const float4*)(b + lane * 4);
    __half2 h0 = __floats2half2_rn((v.x - mu) * rs * gv.x + bv.x,
                                   (v.y - mu) * rs * gv.y + bv.y);
    __half2 h1 = __floats2half2_rn((v.z - mu) * rs * gv.z + bv.z,
                                   (v.w - mu) * rs * gv.w + bv.w);
    uint2 u; u.x = *(uint32_t*)&h0; u.y = *(uint32_t*)&h1;
    *(uint2*)(o + (size_t)row * 128 + lane * 4) = u;
}

__global__ void dist_kernel(const float* __restrict__ coords,
                            const void* __restrict__ ei,
                            float* __restrict__ dist, int E)
{
    int e = blockIdx.x * blockDim.x + threadIdx.x;
    if (e >= E) return;
    int r = edge_idx(ei, e);
    int c = edge_idx(ei, (long long)E + e);
    float dx = coords[r * 3 + 0] - coords[c * 3 + 0];
    float dy = coords[r * 3 + 1] - coords[c * 3 + 1];
    float dz = coords[r * 3 + 2] - coords[c * 3 + 2];
    dist[e] = 0.1f * sqrtf(dx * dx + dy * dy + dz * dz);
}

// edge attention: 16 lanes per edge (2 edges/warp), uint4 loads,
// vector red.global for segment sums.
__global__ void attn_edge_kernel(const __half* __restrict__ qkv,
                                 const __half* __restrict__ ep,
                                 __half* __restrict__ alpha_h,
                                 const void* __restrict__ ei,
                                 float* __restrict__ wV,
                                 float* __restrict__ z,
                                 int E)
{
    const int idx = blockIdx.x * blockDim.x + threadIdx.x;
    const int e = idx >> 4;
    const int l = threadIdx.x & 15;
    if (e >= E) return;
    const int r = edge_idx(ei, e);
    const int c = edge_idx(ei, (long long)E + e);

    const uint4 qu = *(const uint4*)(qkv + (size_t)c * 384 + l * 8);
    const uint4 ku = *(const uint4*)(qkv + (size_t)r * 384 + 128 + l * 8);
    const uint4 vu = *(const uint4*)(qkv + (size_t)r * 384 + 256 + l * 8);
    const uint4 eu = *(const uint4*)(ep + (size_t)e * 128 + l * 8);

    float a[8], vv[8];
    float hs = 0.0f;
    #pragma unroll
    for (int i = 0; i < 4; i++) {
        const uint32_t qw = (&qu.x)[i], kw = (&ku.x)[i];
        const uint32_t vw = (&vu.x)[i], ew = (&eu.x)[i];
        const float2 qf = __half22float2(*(const __half2*)&qw);
        const float2 kf = __half22float2(*(const __half2*)&kw);
        const float2 vf = __half22float2(*(const __half2*)&vw);
        const float2 ef = __half22float2(*(const __half2*)&ew);
        float a0 = fminf(fmaxf(kf.x * qf.x * 0.25f, -5.0f), 5.0f) * ef.x;
        float a1 = fminf(fmaxf(kf.y * qf.y * 0.25f, -5.0f), 5.0f) * ef.y;
        a[i * 2 + 0] = a0; a[i * 2 + 1] = a1;
        vv[i * 2 + 0] = vf.x; vv[i * 2 + 1] = vf.y;
        hs += a0 + a1;
    }

    uint4 au;
    #pragma unroll
    for (int i = 0; i < 4; i++) {
        __half2 h = __floats2half2_rn(a[i * 2], a[i * 2 + 1]);
        (&au.x)[i] = *(uint32_t*)&h;
    }
    *(uint4*)(alpha_h + (size_t)e * 128 + l * 8) = au;

    hs += __shfl_xor_sync(0xffffffffu, hs, 1);
    const float ax = __expf(fminf(fmaxf(hs, -5.0f), 5.0f));

    float* wvp = wV + (size_t)c * 128 + l * 8;
    asm volatile("red.global.add.v4.f32 [%0], {%1, %2, %3, %4};"
                 :: "l"(wvp), "f"(vv[0] * ax), "f"(vv[1] * ax),
                    "f"(vv[2] * ax), "f"(vv[3] * ax) : "memory");
    asm volatile("red.global.add.v4.f32 [%0], {%1, %2, %3, %4};"
                 :: "l"(wvp + 4), "f"(vv[4] * ax), "f"(vv[5] * ax),
                    "f"(vv[6] * ax), "f"(vv[7] * ax) : "memory");
    if ((l & 1) == 0)
        asm volatile("red.global.add.f32 [%0], %1;"
                     :: "l"(z + (size_t)c * 8 + (l >> 1)), "f"(ax) : "memory");
}

__global__ void hattn_kernel(const float* __restrict__ wV,
                             const float* __restrict__ z,
                             __half* __restrict__ out, int N)
{
    int i = blockIdx.x * blockDim.x + threadIdx.x;
    if (i >= N * 128) return;
    int n = i >> 7;
    int h = (i & 127) >> 4;
    out[i] = __float2half_rn(wV[i] / (z[(size_t)n * 8 + h] + 1e-6f));
}

// ---------------------------------------------------------------------------
// Launch (fork/join two-stream schedule, graph-capture compatible)
// ---------------------------------------------------------------------------
extern "C" void kernel_launch(void* const* d_in, const int* in_sizes, int n_in,
                              void* d_out, int out_size)
{
    const float* node_feats = (const float*)d_in[0];
    const float* edge_feats = (const float*)d_in[1];
    const float* coords     = (const float*)d_in[2];
    const void*  ei         = d_in[3];
    const float* Wq   = (const float*)d_in[4];
    const float* Wk   = (const float*)d_in[5];
    const float* Wv   = (const float*)d_in[6];
    const float* We   = (const float*)d_in[7];
    const float* Wo_n = (const float*)d_in[8];
    const float* bo_n = (const float*)d_in[9];
    const float* Wo_e = (const float*)d_in[10];
    const float* bo_e = (const float*)d_in[11];
    const float* ln1n_g = (const float*)d_in[12];
    const float* ln1n_b = (const float*)d_in[13];
    const float* ln1e_g = (const float*)d_in[14];
    const float* ln1e_b = (const float*)d_in[15];
    const float* ln2n_g = (const float*)d_in[16];
    const float* ln2n_b = (const float*)d_in[17];
    const float* ln2e_g = (const float*)d_in[18];
    const float* ln2e_b = (const float*)d_in[19];
    const float* Wn1 = (const float*)d_in[20];
    const float* Wn2 = (const float*)d_in[21];
    const float* We1 = (const float*)d_in[22];
    const float* We2 = (const float*)d_in[23];

    int N = in_sizes[0] / 128;
    int E = in_sizes[1] / 128;

    float* out   = (float*)d_out;
    float* out_n = out;
    float* out_e = out + (size_t)N * 128;

    __half *p_hln, *p_qkv, *p_eln, *p_ep, *p_t, *p_tn, *p_wT;
    float *p_dist, *p_wV, *p_z;
    cudaGetSymbolAddress((void**)&p_hln,  g_hln);
    cudaGetSymbolAddress((void**)&p_qkv,  g_qkv);
    cudaGetSymbolAddress((void**)&p_eln,  g_eln);
    cudaGetSymbolAddress((void**)&p_ep,   g_ep);
    cudaGetSymbolAddress((void**)&p_dist, g_dist);
    cudaGetSymbolAddress((void**)&p_wV,   g_wV);
    cudaGetSymbolAddress((void**)&p_z,    g_z);
    cudaGetSymbolAddress((void**)&p_t,    g_t);
    cudaGetSymbolAddress((void**)&p_tn,   g_tn);
    cudaGetSymbolAddress((void**)&p_wT,   g_wT);

    __half* WqkvT = p_wT + 0;        // [384,128]
    __half* WeT   = p_wT + 49152;    // [128,128]
    __half* WonT  = p_wT + 65536;
    __half* WoeT  = p_wT + 81920;
    __half* Wn1T  = p_wT + 98304;    // [256,128]
    __half* Wn2T  = p_wT + 131072;   // [128,256]
    __half* We1T  = p_wT + 163840;
    __half* We2T  = p_wT + 196608;

    dim3 blk(256);
    cudaStream_t s0 = 0;

    cudaFuncSetAttribute(mma_gemm, cudaFuncAttributeMaxDynamicSharedMemorySize,
                         GEMM_DYN);

    cudaStream_t s2;
    cudaEvent_t evA, evB, evC;
    cudaStreamCreateWithFlags(&s2, cudaStreamNonBlocking);
    cudaEventCreateWithFlags(&evA, cudaEventDisableTiming);
    cudaEventCreateWithFlags(&evB, cudaEventDisableTiming);
    cudaEventCreateWithFlags(&evC, cudaEventDisableTiming);

    detect_kernel<<<1, 32, 0, s0>>>((const int*)ei);

    {
        TransBatch tb;
        const float* srcs[10] = {Wq, Wk, Wv, We, Wo_n, Wo_e, Wn1, Wn2, We1, We2};
        __half* dsts[10] = {WqkvT, WqkvT + 16384, WqkvT + 32768, WeT, WonT, WoeT,
                            Wn1T, Wn2T, We1T, We2T};
        int Rs[10] = {128, 128, 128, 128, 128, 128, 128, 256, 128, 256};
        int Cs[10] = {128, 128, 128, 128, 128, 128, 256, 128, 256, 128};
        for (int i = 0; i < 10; i++) {
            tb.src[i] = srcs[i]; tb.dst[i] = dsts[i]; tb.R[i] = Rs[i]; tb.C[i] = Cs[i];
        }
        transpose_all<<<dim3(8, 8, 10), dim3(32, 8), 0, s0>>>(tb);
    }

    ln2_kernel<<<(N + E + 7) / 8, blk, 0, s0>>>(node_feats, ln1n_g, ln1n_b, p_hln, N,
                                                edge_feats, ln1e_g, ln1e_b, p_eln, E);

    const int gN = (N + 63) / 64;
    const int gE = (E + 63) / 64;

    // ---- fork A: node qkv on s2 concurrent with edge dist/ep on s0 ----
    cudaEventRecord(evA, s0);
    cudaStreamWaitEvent(s2, evA, 0);

    mma_gemm<<<dim3(gN, 3), blk, GEMM_DYN, s2>>>(p_hln, 128, WqkvT, nullptr, p_qkv,
                                          N, 128, 384, nullptr, nullptr, 0,
                                          nullptr, nullptr, 0, nullptr, nullptr, nullptr);

    dist_kernel<<<(E + 255) / 256, blk, 0, s0>>>(coords, ei, p_dist, E);
    cudaMemsetAsync(p_wV, 0, (size_t)N * 128 * sizeof(float), s0);
    cudaMemsetAsync(p_z,  0, (size_t)N * 8 * sizeof(float), s0);
    mma_gemm<<<dim3(gE, 1), blk, GEMM_DYN, s0>>>(p_eln, 128, WeT, nullptr, p_ep,
                                          E, 128, 128, nullptr, nullptr, 0,
                                          p_dist, We + 128 * 128, 0, nullptr, nullptr, nullptr);

    cudaEventRecord(evB, s2);
    cudaStreamWaitEvent(s0, evB, 0);

    attn_edge_kernel<<<(E + 15) / 16, blk, 0, s0>>>(p_qkv, p_ep, p_eln, ei, p_wV, p_z, E);

    // ---- fork B: node path on s2 concurrent with edge path on s0 ----
    cudaEventRecord(evA, s0);
    cudaStreamWaitEvent(s2, evA, 0);

    hattn_kernel<<<(N * 128 + 255) / 256, blk, 0, s2>>>(p_wV, p_z, p_hln, N);
    mma_gemm<<<dim3(gN, 1), blk, GEMM_DYN, s2>>>(p_hln, 128, WonT, out_n, nullptr,
                                          N, 128, 128, bo_n, node_feats, 128,
                                          nullptr, nullptr, 0, ln2n_g, ln2n_b, p_hln);
    mma_gemm<<<dim3(gN, 2), blk, GEMM_DYN, s2>>>(p_hln, 128, Wn1T, nullptr, p_tn,
                                          N, 128, 256, nullptr, nullptr, 0,
                                          nullptr, nullptr, 1, nullptr, nullptr, nullptr);
    mma_gemm<<<dim3(gN, 1), blk, GEMM_DYN, s2>>>(p_tn, 256, Wn2T, out_n, nullptr,
                                          N, 256, 128, nullptr, out_n, 128,
                                          nullptr, nullptr, 0, nullptr, nullptr, nullptr);

    mma_gemm<<<dim3(gE, 1), blk, GEMM_DYN, s0>>>(p_eln, 128, WoeT, out_e, nullptr,
                                          E, 128, 128, bo_e, edge_feats, 128,
                                          nullptr, nullptr, 0, ln2e_g, ln2e_b, p_eln);
    mma_gemm<<<dim3(gE, 2), blk, GEMM_DYN, s0>>>(p_eln, 128, We1T, nullptr, p_t,
                                          E, 128, 256, nullptr, nullptr, 0,
                                          nullptr, nullptr, 1, nullptr, nullptr, nullptr);
    mma_gemm<<<dim3(gE, 1), blk, GEMM_DYN, s0>>>(p_t, 256, We2T, out_e, nullptr,
                                          E, 256, 128, nullptr, out_e, 128,
                                          nullptr, nullptr, 0, nullptr, nullptr, nullptr);

    cudaEventRecord(evC, s2);
    cudaStreamWaitEvent(s0, evC, 0);
}